// round 2
// baseline (speedup 1.0000x reference)
#include <cuda_runtime.h>
#include <cuda_bf16.h>

// Quanvolution (2x2, 4 qubits, RY encoding + RY params + CNOT ring, <Z_q>).
//
// Closed form per output pixel (b,x,y) with patch a00,a01,a10,a11, weights w0..w3:
//   Zq = cos(pi*a_q + w_q)
//   ch0 = Z1*Z2*Z3, ch1 = Z0*Z1, ch2 = Z0*Z1*Z2, ch3 = Z0*Z1*Z2*Z3
//
// This round: fold weights into the shared tile (one Z table per qubit), so
// the inner loop is 4 LDS + 3 FMUL + 4 STG. Single kernel launch (weights
// computed in-block).

#define H_IN 224
#define W_IN 224
#define L_OUT 223          // H_IN - 2 + 1
#define TILE 32            // output tile (TILE x TILE) per block
#define HALO (TILE + 1)    // input tile = 33 x 33
#define HPAD (HALO + 3)    // 36 -> conflict-free rows

__global__ __launch_bounds__(256) void quanv_main_kernel(
    const float* __restrict__ in,   // (64,1,224,224)
    const float* __restrict__ w,    // (1,4)
    float* __restrict__ out)        // (64,4,223,223)
{
    __shared__ float Zt0[HALO][HPAD];
    __shared__ float Zt1[HALO][HPAD];
    __shared__ float Zt2[HALO][HPAD];
    __shared__ float Zt3[HALO][HPAD];
    __shared__ float cws[4], sws[4];

    const int tid = threadIdx.x;

    // Per-block weight trig (cheap; avoids a separate setup kernel launch).
    if (tid < 4) {
        float s, c;
        sincosf(w[tid], &s, &c);
        cws[tid] = c;
        sws[tid] = s;
    }
    __syncthreads();

    const float cw0 = cws[0], sw0 = sws[0];
    const float cw1 = cws[1], sw1 = sws[1];
    const float cw2 = cws[2], sw2 = sws[2];
    const float cw3 = cws[3], sw3 = sws[3];

    const int b  = blockIdx.z;
    const int x0 = blockIdx.y * TILE;
    const int y0 = blockIdx.x * TILE;

    const float* inb = in + (size_t)b * (H_IN * W_IN);

    // Load 33x33 halo tile; per element compute Zq = cos(pi*a)*cw_q - sin(pi*a)*sw_q.
    #pragma unroll
    for (int i = tid; i < HALO * HALO; i += 256) {
        int r = i / HALO;
        int c = i - r * HALO;
        int gx = x0 + r;
        int gy = y0 + c;
        float v = 0.0f;
        if (gx < H_IN && gy < W_IN) v = __ldg(&inb[gx * W_IN + gy]);
        float s, cc;
        sincospif(v, &s, &cc);
        Zt0[r][c] = fmaf(-s, sw0, cc * cw0);
        Zt1[r][c] = fmaf(-s, sw1, cc * cw1);
        Zt2[r][c] = fmaf(-s, sw2, cc * cw2);
        Zt3[r][c] = fmaf(-s, sw3, cc * cw3);
    }
    __syncthreads();

    const int ty  = tid & 31;       // y within tile (warp-contiguous -> coalesced)
    const int tx0 = tid >> 5;       // 0..7, row group
    const int y = y0 + ty;
    if (y >= L_OUT) return;

    const size_t plane = (size_t)L_OUT * L_OUT;
    float* ob = out + (size_t)b * 4 * plane;

    #pragma unroll
    for (int k = 0; k < 4; k++) {
        const int rx = tx0 + k * 8;     // row within tile
        const int x = x0 + rx;
        if (x >= L_OUT) continue;

        const float Z0 = Zt0[rx    ][ty    ];
        const float Z1 = Zt1[rx    ][ty + 1];
        const float Z2 = Zt2[rx + 1][ty    ];
        const float Z3 = Zt3[rx + 1][ty + 1];

        const float p01  = Z0 * Z1;
        const float p12  = Z1 * Z2;
        const float p012 = p01 * Z2;

        float* o = ob + (size_t)x * L_OUT + y;
        o[0]         = p12 * Z3;     // ch0 = Z1 Z2 Z3
        o[plane]     = p01;          // ch1 = Z0 Z1
        o[2 * plane] = p012;         // ch2 = Z0 Z1 Z2
        o[3 * plane] = p012 * Z3;    // ch3 = Z0 Z1 Z2 Z3
    }
}

extern "C" void kernel_launch(void* const* d_in, const int* in_sizes, int n_in,
                              void* d_out, int out_size) {
    const float* inputs = (const float*)d_in[0];   // (64,1,224,224) float32
    const float* weight = (const float*)d_in[1];   // (1,4) float32
    float* out = (float*)d_out;                    // (64,4,223,223) float32

    dim3 grid((L_OUT + TILE - 1) / TILE,   // 7 (y tiles)
              (L_OUT + TILE - 1) / TILE,   // 7 (x tiles)
              64);                          // batch
    quanv_main_kernel<<<grid, 256>>>(inputs, weight, out);
}

// round 3
// speedup vs baseline: 1.2965x; 1.2965x over previous
#include <cuda_runtime.h>
#include <cuda_bf16.h>

// Quanvolution (2x2, 4 qubits, RY encoding + RY params + CNOT ring, <Z_q>).
//
// Closed form per output pixel (b,x,y) with patch a00,a01,a10,a11, weights w0..w3:
//   Zq = cos(pi*a_q + w_q) = cos(pi a_q) cos(w_q) - sin(pi a_q) sin(w_q)
//   ch0 = Z1*Z2*Z3, ch1 = Z0*Z1, ch2 = Z0*Z1*Z2, ch3 = Z0*Z1*Z2*Z3
//
// R3: MUFU trig (__sincosf, arg in [0,pi) -> ~4e-7 abs err, well within 1e-3),
// float2-packed (cos,sin) shared tile (LDS.64), single kernel, single barrier.

#define H_IN 224
#define W_IN 224
#define L_OUT 223          // H_IN - 2 + 1
#define TILE 32            // output tile (TILE x TILE) per block
#define HALO (TILE + 1)    // input tile = 33 x 33
#define HPAD (HALO + 3)    // float2 row stride = 36 -> conflict-free

#define PI_F 3.14159265358979323846f

__global__ __launch_bounds__(256) void quanv_main_kernel(
    const float* __restrict__ in,   // (64,1,224,224)
    const float* __restrict__ w,    // (1,4)
    float* __restrict__ out)        // (64,4,223,223)
{
    __shared__ float2 CS[HALO][HPAD];
    __shared__ float cws[4], sws[4];

    const int tid = threadIdx.x;
    const int b  = blockIdx.z;
    const int x0 = blockIdx.y * TILE;
    const int y0 = blockIdx.x * TILE;

    // Weight trig via MUFU: cheap, overlaps with the tile load below,
    // synchronized by the same barrier.
    if (tid < 4) {
        float s, c;
        __sincosf(w[tid], &s, &c);
        cws[tid] = c;
        sws[tid] = s;
    }

    const float* inb = in + (size_t)b * (H_IN * W_IN);

    // Load 33x33 halo tile; per element store (cos(pi a), sin(pi a)) as float2.
    #pragma unroll
    for (int i = tid; i < HALO * HALO; i += 256) {
        int r = i / HALO;
        int c = i - r * HALO;
        int gx = x0 + r;
        int gy = y0 + c;
        float v = 0.0f;
        if (gx < H_IN && gy < W_IN) v = __ldg(&inb[gx * W_IN + gy]);
        float s, cc;
        __sincosf(v * PI_F, &s, &cc);   // MUFU path; arg in [0, pi)
        CS[r][c] = make_float2(cc, s);
    }
    __syncthreads();

    const float cw0 = cws[0], sw0 = sws[0];
    const float cw1 = cws[1], sw1 = sws[1];
    const float cw2 = cws[2], sw2 = sws[2];
    const float cw3 = cws[3], sw3 = sws[3];

    const int ty  = tid & 31;       // y within tile (warp-contiguous -> coalesced STG)
    const int tx0 = tid >> 5;       // 0..7, row group
    const int y = y0 + ty;
    if (y >= L_OUT) return;         // after barrier: safe

    const size_t plane = (size_t)L_OUT * L_OUT;
    float* o = out + (size_t)b * 4 * plane + (size_t)(x0 + tx0) * L_OUT + y;

    #pragma unroll
    for (int k = 0; k < 4; k++) {
        const int rx = tx0 + 8 * k;     // row within tile
        if (x0 + rx < L_OUT) {
            const float2 a00 = CS[rx    ][ty    ];
            const float2 a01 = CS[rx    ][ty + 1];
            const float2 a10 = CS[rx + 1][ty    ];
            const float2 a11 = CS[rx + 1][ty + 1];

            const float Z0 = fmaf(-a00.y, sw0, a00.x * cw0);
            const float Z1 = fmaf(-a01.y, sw1, a01.x * cw1);
            const float Z2 = fmaf(-a10.y, sw2, a10.x * cw2);
            const float Z3 = fmaf(-a11.y, sw3, a11.x * cw3);

            const float p01 = Z0 * Z1;
            const float p23 = Z2 * Z3;

            o[0]         = Z1 * p23;     // ch0 = Z1 Z2 Z3
            o[plane]     = p01;          // ch1 = Z0 Z1
            o[2 * plane] = p01 * Z2;     // ch2 = Z0 Z1 Z2
            o[3 * plane] = p01 * p23;    // ch3 = Z0 Z1 Z2 Z3
        }
        o += 8 * L_OUT;                  // next row group
    }
}

extern "C" void kernel_launch(void* const* d_in, const int* in_sizes, int n_in,
                              void* d_out, int out_size) {
    const float* inputs = (const float*)d_in[0];   // (64,1,224,224) float32
    const float* weight = (const float*)d_in[1];   // (1,4) float32
    float* out = (float*)d_out;                    // (64,4,223,223) float32

    dim3 grid((L_OUT + TILE - 1) / TILE,   // 7 (y tiles)
              (L_OUT + TILE - 1) / TILE,   // 7 (x tiles)
              64);                          // batch
    quanv_main_kernel<<<grid, 256>>>(inputs, weight, out);
}